// round 13
// baseline (speedup 1.0000x reference)
#include <cuda_runtime.h>
#include <cuda_fp16.h>
#include <math.h>

#define NN 50000
#define EE 800000
#define IND 128
#define EDIM 16
#define HH 8
#define HD 64

#define K23_EPB 256                    // 8 warps x 32 edges (4 per lane-group)
#define K23_GRID (EE / K23_EPB)        // 3125
#define PREP_GRID 3125                 // 256 edges per block
#define EXP_OFS 30.0f

// ---------------- scratch (device globals: no allocation allowed) ----------------
__device__ __align__(16) __half g_half[NN * HD];    // fp16 g (6.4 MB) — the only g buffer
__device__ __align__(16) float  S_buf[NN * HH];     // 1.6 MB
__device__ __align__(16) float  Gmat_d[HD * IND];
__device__ __align__(16) float  Mmat_d[HH * EDIM];
__device__ __align__(128) float Zpad[HH * 32];      // one head per 128B line
__device__ __align__(16) int2   idx2_buf[EE];       // packed (src,dst)

__device__ __forceinline__ float hdot8(uint4 ua, uint4 ub) {
    float2 a, b; float d = 0.f;
    a = __half22float2(*(__half2*)&ua.x); b = __half22float2(*(__half2*)&ub.x); d += a.x*b.x + a.y*b.y;
    a = __half22float2(*(__half2*)&ua.y); b = __half22float2(*(__half2*)&ub.y); d += a.x*b.x + a.y*b.y;
    a = __half22float2(*(__half2*)&ua.z); b = __half22float2(*(__half2*)&ub.z); d += a.x*b.x + a.y*b.y;
    a = __half22float2(*(__half2*)&ua.w); b = __half22float2(*(__half2*)&ub.w); d += a.x*b.x + a.y*b.y;
    return d;
}

// ---------------- prep: 1 edge/thread, full-width blocks ----------------
__global__ __launch_bounds__(256) void k_prep(const void* __restrict__ p,
                                              const float* __restrict__ W,
                                              const float* __restrict__ W_edge,
                                              const float* __restrict__ W_edge_att,
                                              const float* __restrict__ W_att) {
    __shared__ int s64;
    int tid = threadIdx.x;
    int b = blockIdx.x;

    // int64-vs-int32 detection (jnp.int64 silently becomes int32 when x64 off):
    // true int64 (<2^31) => every odd 32-bit word is 0; 32 zero high words is conclusive.
    if (tid < 32) {
        unsigned int v = ((const unsigned int*)p)[2 * tid + 1];
        unsigned int ball = __ballot_sync(0xffffffffu, v == 0u);
        if (tid == 0) s64 = (ball == 0xffffffffu) ? 1 : 0;
    }
    __syncthreads();
    int is64 = s64;

    // one edge per thread: coalesced loads
    {
        int e = b * 256 + tid;
        int src, dst;
        if (is64) { src = (int)((const long long*)p)[e]; dst = (int)((const long long*)p)[EE + e]; }
        else      { src = ((const int*)p)[e];            dst = ((const int*)p)[EE + e]; }
        idx2_buf[e] = make_int2(src, dst);
    }

    // zero S: 400000 floats / 3125 blocks = 128 per block (32 float4)
    if (tid < 32) {
        *(float4*)(S_buf + b * 128 + tid * 4) = make_float4(0.f, 0.f, 0.f, 0.f);
    }

    if (b == 0) {
        if (tid < HH * 32) Zpad[tid] = 0.f;
        if (tid < HH * EDIM) {
            int h = tid / EDIM, c = tid % EDIM;
            float s = 0.f;
            #pragma unroll 8
            for (int j = 0; j < 64; j++) s += W_edge_att[h * 64 + j] * W_edge[j * EDIM + c];
            Mmat_d[tid] = s;
        }
        // Gmat[h*8+k][i] = sum_d W_att[k,d] * W[h*8+d, i]
        for (int idx = tid; idx < HD * IND; idx += 256) {
            int j = idx / IND, c = idx % IND;
            int h = j / 8, k = j % 8;
            float s = 0.f;
            #pragma unroll
            for (int d = 0; d < 8; d++) s += W_att[k * 8 + d] * W[(h * 8 + d) * IND + c];
            Gmat_d[idx] = s;
        }
    }
}

// ---------------- k1: g = x @ Gmat^T, 64x64 tiles (finer wave quantization) ----------------
__global__ __launch_bounds__(256) void k1(const float* __restrict__ x) {
    __shared__ float sx[64][33];
    __shared__ float sg[64][33];
    int tid = threadIdx.x;
    int n0 = blockIdx.x * 64;
    int tr = (tid / 16) * 4;   // 16 row groups x 4 rows
    int tc = (tid % 16) * 4;   // 16 col groups x 4 cols
    float acc[4][4];
    #pragma unroll
    for (int r = 0; r < 4; r++)
        #pragma unroll
        for (int c = 0; c < 4; c++) acc[r][c] = 0.f;

    for (int kc = 0; kc < IND; kc += 32) {
        // x tile: 64 rows x 32 cols = 512 float4, 2 per thread
        #pragma unroll
        for (int l = tid; l < 64 * 8; l += 256) {
            int r = l / 8, c4 = (l % 8) * 4;
            int gr = n0 + r;
            float4 v = (gr < NN) ? *(const float4*)(x + (size_t)gr * IND + kc + c4)
                                 : make_float4(0.f, 0.f, 0.f, 0.f);
            sx[r][c4] = v.x; sx[r][c4 + 1] = v.y; sx[r][c4 + 2] = v.z; sx[r][c4 + 3] = v.w;
        }
        #pragma unroll
        for (int l = tid; l < 64 * 8; l += 256) {
            int r = l / 8, c4 = (l % 8) * 4;
            float4 v = *(const float4*)(Gmat_d + r * IND + kc + c4);
            sg[r][c4] = v.x; sg[r][c4 + 1] = v.y; sg[r][c4 + 2] = v.z; sg[r][c4 + 3] = v.w;
        }
        __syncthreads();
        #pragma unroll 8
        for (int k = 0; k < 32; k++) {
            float gv[4];
            #pragma unroll
            for (int c = 0; c < 4; c++) gv[c] = sg[tc + c][k];
            #pragma unroll
            for (int r = 0; r < 4; r++) {
                float xv = sx[tr + r][k];
                #pragma unroll
                for (int c = 0; c < 4; c++) acc[r][c] += xv * gv[c];
            }
        }
        __syncthreads();
    }
    #pragma unroll
    for (int r = 0; r < 4; r++) {
        int gr = n0 + tr + r;
        if (gr < NN) {
            __half2* hp = (__half2*)(g_half + (size_t)gr * HD + tc);
            hp[0] = __floats2half2_rn(acc[r][0], acc[r][1]);
            hp[1] = __floats2half2_rn(acc[r][2], acc[r][3]);
        }
    }
}

// ---------------- k23: 32 edges/warp (4 per lane-group) ----------------
__global__ __launch_bounds__(256) void k23(const float* __restrict__ edge_attr) {
    __shared__ float sM2[EDIM * 9 + 8];   // sM2[c*9 + h]
    __shared__ float sz[8][HH];
    int tid = threadIdx.x;
    if (tid < EDIM * HH) {
        int c = tid / HH, h = tid % HH;
        sM2[c * 9 + h] = Mmat_d[h * EDIM + c];
    }
    __syncthreads();

    int lane = tid & 31, wid = tid >> 5;
    int j = lane & 3, g = lane >> 2;
    int h0 = 2 * j, h1 = 2 * j + 1;
    int eb = blockIdx.x * K23_EPB + wid * 32 + g;   // edges eb, eb+8, eb+16, eb+24

    int2 sd[4];
    #pragma unroll
    for (int i = 0; i < 4; i++) sd[i] = __ldcs(idx2_buf + eb + 8 * i);

    float4 aq[4];
    #pragma unroll
    for (int i = 0; i < 4; i++)
        aq[i] = __ldcs((const float4*)(edge_attr + (size_t)(eb + 8 * i) * EDIM) + j);

    uint4 ua0[4], ua1[4], ub0[4], ub1[4];
    #pragma unroll
    for (int i = 0; i < 4; i++) {
        const uint4* gs = (const uint4*)(g_half + (size_t)sd[i].x * HD);
        const uint4* gd = (const uint4*)(g_half + (size_t)sd[i].y * HD);
        ua0[i] = gs[h0]; ua1[i] = gs[h1];
        ub0[i] = gd[h0]; ub1[i] = gd[h1];
    }

    const float* mrow = sM2 + 4 * j * 9;
    bool hi = (j & 2) != 0;
    bool odd = (j & 1) != 0;
    float ea0[4], ea1[4];
    #pragma unroll
    for (int i = 0; i < 4; i++) {
        float eL[4], eH[4];
        #pragma unroll
        for (int h = 0; h < 4; h++) {
            eL[h] = aq[i].x * mrow[h]     + aq[i].y * mrow[9 + h]  + aq[i].z * mrow[18 + h] + aq[i].w * mrow[27 + h];
            eH[h] = aq[i].x * mrow[4 + h] + aq[i].y * mrow[13 + h] + aq[i].z * mrow[22 + h] + aq[i].w * mrow[31 + h];
        }
        float r[4];
        #pragma unroll
        for (int h = 0; h < 4; h++) {
            float mine = hi ? eH[h] : eL[h];
            float send = hi ? eL[h] : eH[h];
            r[h] = mine + __shfl_xor_sync(0xffffffffu, send, 2);
        }
        float m0 = odd ? r[2] : r[0], s0 = odd ? r[0] : r[2];
        float m1 = odd ? r[3] : r[1], s1 = odd ? r[1] : r[3];
        ea0[i] = m0 + __shfl_xor_sync(0xffffffffu, s0, 1);
        ea1[i] = m1 + __shfl_xor_sync(0xffffffffu, s1, 1);
    }

    float p0[4], p1[4];
    #pragma unroll
    for (int i = 0; i < 4; i++) {
        float s0 = hdot8(ua0[i], ub0[i]) + 8.f * ea0[i];
        float s1 = hdot8(ua1[i], ub1[i]) + 8.f * ea1[i];
        s0 = (s0 > 0.f) ? s0 : 0.2f * s0;
        s1 = (s1 > 0.f) ? s1 : 0.2f * s1;
        p0[i] = __expf(s0 - EXP_OFS);
        p1[i] = __expf(s1 - EXP_OFS);
    }

    #pragma unroll
    for (int i = 0; i < 4; i++) {
        float q0 = __shfl_xor_sync(0xffffffffu, p0[i], 1);
        float q1 = __shfl_xor_sync(0xffffffffu, p1[i], 1);
        if ((j & 1) == 0) {
            float* sp = S_buf + (size_t)sd[i].y * 8 + j * 2;
            asm volatile("red.global.add.v4.f32 [%0], {%1,%2,%3,%4};"
                         :: "l"(sp), "f"(p0[i]), "f"(p1[i]), "f"(q0), "f"(q1) : "memory");
        }
    }

    float z0 = p0[0] + p0[1] + p0[2] + p0[3];
    float z1 = p1[0] + p1[1] + p1[2] + p1[3];
    #pragma unroll
    for (int o = 4; o <= 16; o <<= 1) {
        z0 += __shfl_xor_sync(0xffffffffu, z0, o);
        z1 += __shfl_xor_sync(0xffffffffu, z1, o);
    }
    if (lane < 4) {
        sz[wid][2 * lane]     = z0;
        sz[wid][2 * lane + 1] = z1;
    }
    __syncthreads();
    if (tid < 8) {
        float s = 0.f;
        #pragma unroll
        for (int w = 0; w < 8; w++) s += sz[w][tid];
        atomicAdd(&Zpad[tid * 32], s);
    }
}

// ---------------- k4: epilogue from fp16 g ----------------
__global__ __launch_bounds__(128) void k4(const float* __restrict__ W_out, float* __restrict__ out) {
    __shared__ float sw[8 * 68];       // sw[h*68 + k*8 + d]
    __shared__ float sinvZ[8];
    int tid = threadIdx.x;
    for (int i = tid; i < 512; i += 128) {
        int k = i / 64, r = i % 64;
        int h = r / 8, d = r % 8;
        sw[h * 68 + k * 8 + d] = W_out[i];
    }
    if (tid < 8) sinvZ[tid] = 1.0f / Zpad[tid * 32];
    __syncthreads();

    int lane = tid & 31, wid = tid >> 5;
    int j = lane & 3;
    int n = blockIdx.x * 32 + wid * 8 + (lane >> 2);
    int nc = (n < NN) ? n : (NN - 1);
    int h0 = 2 * j, h1 = 2 * j + 1;

    const uint4* gp = (const uint4*)(g_half + (size_t)nc * HD);
    uint4 U0 = gp[h0], U1 = gp[h1];
    float2 S2 = *(const float2*)(S_buf + (size_t)nc * 8 + 2 * j);
    float sv0 = S2.x * sinvZ[h0];
    float sv1 = S2.y * sinvZ[h1];

    float2 a0 = __half22float2(*(__half2*)&U0.x), a1 = __half22float2(*(__half2*)&U0.y);
    float2 a2 = __half22float2(*(__half2*)&U0.z), a3 = __half22float2(*(__half2*)&U0.w);
    float2 b0 = __half22float2(*(__half2*)&U1.x), b1 = __half22float2(*(__half2*)&U1.y);
    float2 b2 = __half22float2(*(__half2*)&U1.z), b3 = __half22float2(*(__half2*)&U1.w);

    float ga[8] = { a0.x*sv0, a0.y*sv0, a1.x*sv0, a1.y*sv0, a2.x*sv0, a2.y*sv0, a3.x*sv0, a3.y*sv0 };
    float gb[8] = { b0.x*sv1, b0.y*sv1, b1.x*sv1, b1.y*sv1, b2.x*sv1, b2.y*sv1, b3.x*sv1, b3.y*sv1 };

    float acc[8];
    #pragma unroll
    for (int k = 0; k < 8; k++) {
        const float* w0 = sw + h0 * 68 + k * 8;
        const float* w1 = sw + h1 * 68 + k * 8;
        float s = 0.f;
        #pragma unroll
        for (int d = 0; d < 8; d++) s += ga[d] * w0[d] + gb[d] * w1[d];
        acc[k] = s;
    }
    #pragma unroll
    for (int o = 1; o <= 2; o <<= 1)
        #pragma unroll
        for (int k = 0; k < 8; k++) acc[k] += __shfl_xor_sync(0xffffffffu, acc[k], o);

    if (n < NN) {
        float2 r;
        r.x = fmaxf(acc[2 * j], 0.f);
        r.y = fmaxf(acc[2 * j + 1], 0.f);
        *(float2*)(out + (size_t)n * 8 + 2 * j) = r;
    }
}

// ---------------- launch ----------------
extern "C" void kernel_launch(void* const* d_in, const int* in_sizes, int n_in,
                              void* d_out, int out_size) {
    const float* x          = (const float*)d_in[0];
    const float* edge_attr  = (const float*)d_in[1];
    const float* W          = (const float*)d_in[2];
    const float* W_edge     = (const float*)d_in[3];
    const float* W_edge_att = (const float*)d_in[4];
    const float* W_att      = (const float*)d_in[5];
    const float* W_out      = (const float*)d_in[6];
    const void*  ei         = d_in[7];
    float* out = (float*)d_out;
    (void)in_sizes; (void)n_in; (void)out_size;

    k_prep<<<PREP_GRID, 256>>>(ei, W, W_edge, W_edge_att, W_att);
    k1<<<(NN + 63) / 64, 256>>>(x);
    k23<<<K23_GRID, 256>>>(edge_attr);
    k4<<<(NN + 31) / 32, 128>>>(W_out, out);
}

// round 14
// speedup vs baseline: 1.1315x; 1.1315x over previous
#include <cuda_runtime.h>
#include <cuda_fp16.h>
#include <math.h>

#define NN 50000
#define EE 800000
#define IND 128
#define EDIM 16
#define HH 8
#define HD 64

#define K23_EPB 256                    // 8 warps x 32 edges (4 per lane-group)
#define K23_GRID (EE / K23_EPB)        // 3125
#define PREP_GRID 6250
#define EXP_OFS 30.0f

// ---------------- scratch (device globals: no allocation allowed) ----------------
__device__ __align__(16) __half g_half[NN * HD];    // fp16 g (6.4 MB) — the only g buffer
__device__ __align__(16) float  S_buf[NN * HH];     // 1.6 MB
__device__ __align__(16) float  Gmat_d[HD * IND];
__device__ __align__(16) float  Mmat_d[HH * EDIM];
__device__ __align__(128) float Zpad[HH * 32];      // one head per 128B line
__device__ __align__(16) int2   idx2_buf[EE];       // packed (src,dst)

__device__ __forceinline__ float hdot8(uint4 ua, uint4 ub) {
    float2 a, b; float d = 0.f;
    a = __half22float2(*(__half2*)&ua.x); b = __half22float2(*(__half2*)&ub.x); d += a.x*b.x + a.y*b.y;
    a = __half22float2(*(__half2*)&ua.y); b = __half22float2(*(__half2*)&ub.y); d += a.x*b.x + a.y*b.y;
    a = __half22float2(*(__half2*)&ua.z); b = __half22float2(*(__half2*)&ub.z); d += a.x*b.x + a.y*b.y;
    a = __half22float2(*(__half2*)&ua.w); b = __half22float2(*(__half2*)&ub.w); d += a.x*b.x + a.y*b.y;
    return d;
}

// ---------------- fused prep: idx normalize+pack, zero S/Z, fold weights ----------------
__global__ __launch_bounds__(256) void k_prep(const void* __restrict__ p,
                                              const float* __restrict__ W,
                                              const float* __restrict__ W_edge,
                                              const float* __restrict__ W_edge_att,
                                              const float* __restrict__ W_att) {
    __shared__ int s64;
    int tid = threadIdx.x;
    int b = blockIdx.x;

    // int64-vs-int32 detection (jnp.int64 silently becomes int32 when x64 off):
    // true int64 (<2^31) => every odd 32-bit word is 0; 32 zero high words is conclusive.
    if (tid < 32) {
        unsigned int v = ((const unsigned int*)p)[2 * tid + 1];
        unsigned int ball = __ballot_sync(0xffffffffu, v == 0u);
        if (tid == 0) s64 = (ball == 0xffffffffu) ? 1 : 0;
    }
    __syncthreads();
    int is64 = s64;

    if (tid < 128) {
        int e = b * 128 + tid;
        int src, dst;
        if (is64) { src = (int)((const long long*)p)[e]; dst = (int)((const long long*)p)[EE + e]; }
        else      { src = ((const int*)p)[e];            dst = ((const int*)p)[EE + e]; }
        idx2_buf[e] = make_int2(src, dst);
    }

    if (tid < 16) {
        int zi = b * 64 + tid * 4;
        *(float4*)(S_buf + zi) = make_float4(0.f, 0.f, 0.f, 0.f);
    }

    if (b == 0) {
        if (tid < HH * 32) Zpad[tid] = 0.f;
        if (tid < HH * EDIM) {
            int h = tid / EDIM, c = tid % EDIM;
            float s = 0.f;
            #pragma unroll 8
            for (int j = 0; j < 64; j++) s += W_edge_att[h * 64 + j] * W_edge[j * EDIM + c];
            Mmat_d[tid] = s;
        }
        // Gmat[h*8+k][i] = sum_d W_att[k,d] * W[h*8+d, i]
        for (int idx = tid; idx < HD * IND; idx += 256) {
            int j = idx / IND, c = idx % IND;
            int h = j / 8, k = j % 8;
            float s = 0.f;
            #pragma unroll
            for (int d = 0; d < 8; d++) s += W_att[k * 8 + d] * W[(h * 8 + d) * IND + c];
            Gmat_d[idx] = s;
        }
    }
}

// ---------------- k1: g = x @ Gmat^T  ([N,128] -> [N,64]), fp16-only output ----------------
__global__ __launch_bounds__(256) void k1(const float* __restrict__ x) {
    __shared__ float sx[128][33];
    __shared__ float sg[64][33];
    int tid = threadIdx.x;
    int n0 = blockIdx.x * 128;
    int tr = (tid / 16) * 8;
    int tc = (tid % 16) * 4;
    float acc[8][4];
    #pragma unroll
    for (int r = 0; r < 8; r++)
        #pragma unroll
        for (int c = 0; c < 4; c++) acc[r][c] = 0.f;

    for (int kc = 0; kc < IND; kc += 32) {
        for (int l = tid; l < 128 * 8; l += 256) {
            int r = l / 8, c4 = (l % 8) * 4;
            int gr = n0 + r;
            float4 v = (gr < NN) ? *(const float4*)(x + (size_t)gr * IND + kc + c4)
                                 : make_float4(0.f, 0.f, 0.f, 0.f);
            sx[r][c4] = v.x; sx[r][c4 + 1] = v.y; sx[r][c4 + 2] = v.z; sx[r][c4 + 3] = v.w;
        }
        for (int l = tid; l < 64 * 8; l += 256) {
            int r = l / 8, c4 = (l % 8) * 4;
            float4 v = *(const float4*)(Gmat_d + r * IND + kc + c4);
            sg[r][c4] = v.x; sg[r][c4 + 1] = v.y; sg[r][c4 + 2] = v.z; sg[r][c4 + 3] = v.w;
        }
        __syncthreads();
        #pragma unroll 8
        for (int k = 0; k < 32; k++) {
            float gv[4];
            #pragma unroll
            for (int c = 0; c < 4; c++) gv[c] = sg[tc + c][k];
            #pragma unroll
            for (int r = 0; r < 8; r++) {
                float xv = sx[tr + r][k];
                #pragma unroll
                for (int c = 0; c < 4; c++) acc[r][c] += xv * gv[c];
            }
        }
        __syncthreads();
    }
    #pragma unroll
    for (int r = 0; r < 8; r++) {
        int gr = n0 + tr + r;
        if (gr < NN) {
            __half2* hp = (__half2*)(g_half + (size_t)gr * HD + tc);
            hp[0] = __floats2half2_rn(acc[r][0], acc[r][1]);
            hp[1] = __floats2half2_rn(acc[r][2], acc[r][3]);
        }
    }
}

// ---------------- k23: 32 edges/warp (4 per lane-group) ----------------
__global__ __launch_bounds__(256) void k23(const float* __restrict__ edge_attr) {
    __shared__ float sM2[EDIM * 9 + 8];   // sM2[c*9 + h]
    __shared__ float sz[8][HH];
    int tid = threadIdx.x;
    if (tid < EDIM * HH) {
        int c = tid / HH, h = tid % HH;
        sM2[c * 9 + h] = Mmat_d[h * EDIM + c];
    }
    __syncthreads();

    int lane = tid & 31, wid = tid >> 5;
    int j = lane & 3, g = lane >> 2;
    int h0 = 2 * j, h1 = 2 * j + 1;
    int eb = blockIdx.x * K23_EPB + wid * 32 + g;   // edges eb, eb+8, eb+16, eb+24

    int2 sd[4];
    #pragma unroll
    for (int i = 0; i < 4; i++) sd[i] = __ldcs(idx2_buf + eb + 8 * i);

    float4 aq[4];
    #pragma unroll
    for (int i = 0; i < 4; i++)
        aq[i] = __ldcs((const float4*)(edge_attr + (size_t)(eb + 8 * i) * EDIM) + j);

    uint4 ua0[4], ua1[4], ub0[4], ub1[4];
    #pragma unroll
    for (int i = 0; i < 4; i++) {
        const uint4* gs = (const uint4*)(g_half + (size_t)sd[i].x * HD);
        const uint4* gd = (const uint4*)(g_half + (size_t)sd[i].y * HD);
        ua0[i] = gs[h0]; ua1[i] = gs[h1];
        ub0[i] = gd[h0]; ub1[i] = gd[h1];
    }

    const float* mrow = sM2 + 4 * j * 9;
    bool hi = (j & 2) != 0;
    bool odd = (j & 1) != 0;
    float ea0[4], ea1[4];
    #pragma unroll
    for (int i = 0; i < 4; i++) {
        float eL[4], eH[4];
        #pragma unroll
        for (int h = 0; h < 4; h++) {
            eL[h] = aq[i].x * mrow[h]     + aq[i].y * mrow[9 + h]  + aq[i].z * mrow[18 + h] + aq[i].w * mrow[27 + h];
            eH[h] = aq[i].x * mrow[4 + h] + aq[i].y * mrow[13 + h] + aq[i].z * mrow[22 + h] + aq[i].w * mrow[31 + h];
        }
        float r[4];
        #pragma unroll
        for (int h = 0; h < 4; h++) {
            float mine = hi ? eH[h] : eL[h];
            float send = hi ? eL[h] : eH[h];
            r[h] = mine + __shfl_xor_sync(0xffffffffu, send, 2);
        }
        float m0 = odd ? r[2] : r[0], s0 = odd ? r[0] : r[2];
        float m1 = odd ? r[3] : r[1], s1 = odd ? r[1] : r[3];
        ea0[i] = m0 + __shfl_xor_sync(0xffffffffu, s0, 1);
        ea1[i] = m1 + __shfl_xor_sync(0xffffffffu, s1, 1);
    }

    float p0[4], p1[4];
    #pragma unroll
    for (int i = 0; i < 4; i++) {
        float s0 = hdot8(ua0[i], ub0[i]) + 8.f * ea0[i];
        float s1 = hdot8(ua1[i], ub1[i]) + 8.f * ea1[i];
        s0 = (s0 > 0.f) ? s0 : 0.2f * s0;
        s1 = (s1 > 0.f) ? s1 : 0.2f * s1;
        p0[i] = __expf(s0 - EXP_OFS);
        p1[i] = __expf(s1 - EXP_OFS);
    }

    #pragma unroll
    for (int i = 0; i < 4; i++) {
        float q0 = __shfl_xor_sync(0xffffffffu, p0[i], 1);
        float q1 = __shfl_xor_sync(0xffffffffu, p1[i], 1);
        if ((j & 1) == 0) {
            float* sp = S_buf + (size_t)sd[i].y * 8 + j * 2;
            asm volatile("red.global.add.v4.f32 [%0], {%1,%2,%3,%4};"
                         :: "l"(sp), "f"(p0[i]), "f"(p1[i]), "f"(q0), "f"(q1) : "memory");
        }
    }

    float z0 = p0[0] + p0[1] + p0[2] + p0[3];
    float z1 = p1[0] + p1[1] + p1[2] + p1[3];
    #pragma unroll
    for (int o = 4; o <= 16; o <<= 1) {
        z0 += __shfl_xor_sync(0xffffffffu, z0, o);
        z1 += __shfl_xor_sync(0xffffffffu, z1, o);
    }
    if (lane < 4) {
        sz[wid][2 * lane]     = z0;
        sz[wid][2 * lane + 1] = z1;
    }
    __syncthreads();
    if (tid < 8) {
        float s = 0.f;
        #pragma unroll
        for (int w = 0; w < 8; w++) s += sz[w][tid];
        atomicAdd(&Zpad[tid * 32], s);
    }
}

// ---------------- k4: epilogue from fp16 g ----------------
__global__ __launch_bounds__(128) void k4(const float* __restrict__ W_out, float* __restrict__ out) {
    __shared__ float sw[8 * 68];       // sw[h*68 + k*8 + d]
    __shared__ float sinvZ[8];
    int tid = threadIdx.x;
    for (int i = tid; i < 512; i += 128) {
        int k = i / 64, r = i % 64;
        int h = r / 8, d = r % 8;
        sw[h * 68 + k * 8 + d] = W_out[i];
    }
    if (tid < 8) sinvZ[tid] = 1.0f / Zpad[tid * 32];
    __syncthreads();

    int lane = tid & 31, wid = tid >> 5;
    int j = lane & 3;
    int n = blockIdx.x * 32 + wid * 8 + (lane >> 2);
    int nc = (n < NN) ? n : (NN - 1);
    int h0 = 2 * j, h1 = 2 * j + 1;

    const uint4* gp = (const uint4*)(g_half + (size_t)nc * HD);
    uint4 U0 = gp[h0], U1 = gp[h1];
    float2 S2 = *(const float2*)(S_buf + (size_t)nc * 8 + 2 * j);
    float sv0 = S2.x * sinvZ[h0];
    float sv1 = S2.y * sinvZ[h1];

    float2 a0 = __half22float2(*(__half2*)&U0.x), a1 = __half22float2(*(__half2*)&U0.y);
    float2 a2 = __half22float2(*(__half2*)&U0.z), a3 = __half22float2(*(__half2*)&U0.w);
    float2 b0 = __half22float2(*(__half2*)&U1.x), b1 = __half22float2(*(__half2*)&U1.y);
    float2 b2 = __half22float2(*(__half2*)&U1.z), b3 = __half22float2(*(__half2*)&U1.w);

    float ga[8] = { a0.x*sv0, a0.y*sv0, a1.x*sv0, a1.y*sv0, a2.x*sv0, a2.y*sv0, a3.x*sv0, a3.y*sv0 };
    float gb[8] = { b0.x*sv1, b0.y*sv1, b1.x*sv1, b1.y*sv1, b2.x*sv1, b2.y*sv1, b3.x*sv1, b3.y*sv1 };

    float acc[8];
    #pragma unroll
    for (int k = 0; k < 8; k++) {
        const float* w0 = sw + h0 * 68 + k * 8;
        const float* w1 = sw + h1 * 68 + k * 8;
        float s = 0.f;
        #pragma unroll
        for (int d = 0; d < 8; d++) s += ga[d] * w0[d] + gb[d] * w1[d];
        acc[k] = s;
    }
    #pragma unroll
    for (int o = 1; o <= 2; o <<= 1)
        #pragma unroll
        for (int k = 0; k < 8; k++) acc[k] += __shfl_xor_sync(0xffffffffu, acc[k], o);

    if (n < NN) {
        float2 r;
        r.x = fmaxf(acc[2 * j], 0.f);
        r.y = fmaxf(acc[2 * j + 1], 0.f);
        *(float2*)(out + (size_t)n * 8 + 2 * j) = r;
    }
}

// ---------------- launch ----------------
extern "C" void kernel_launch(void* const* d_in, const int* in_sizes, int n_in,
                              void* d_out, int out_size) {
    const float* x          = (const float*)d_in[0];
    const float* edge_attr  = (const float*)d_in[1];
    const float* W          = (const float*)d_in[2];
    const float* W_edge     = (const float*)d_in[3];
    const float* W_edge_att = (const float*)d_in[4];
    const float* W_att      = (const float*)d_in[5];
    const float* W_out      = (const float*)d_in[6];
    const void*  ei         = d_in[7];
    float* out = (float*)d_out;
    (void)in_sizes; (void)n_in; (void)out_size;

    k_prep<<<PREP_GRID, 256>>>(ei, W, W_edge, W_edge_att, W_att);
    k1<<<(NN + 127) / 128, 256>>>(x);
    k23<<<K23_GRID, 256>>>(edge_attr);
    k4<<<(NN + 31) / 32, 128>>>(W_out, out);
}